// round 17
// baseline (speedup 1.0000x reference)
#include <cuda_runtime.h>
#include <cuda_fp16.h>
#include <cstdint>

// Problem dims
#define BATCH 8
#define SEQ   2048
#define EMB   1024
#define HEAD  128
#define MROWS (BATCH * SEQ)     // 16384
#define NTILES (MROWS / 128)    // 128
#define TILE_ELE (128 * 128)

// fp16 projected tensors, row-major per 128x128 tile.
// Q: [m][h]. K: [n][h]. V: TRANSPOSED [h][n].
__device__ __half g_q[NTILES * TILE_ELE];
__device__ __half g_k[NTILES * TILE_ELE];
__device__ __half g_v[NTILES * TILE_ELE];

// fp16 weights: [w][n][k], k contiguous
__device__ __half g_w[3 * 128 * 1024];

// Per-batch completion counters (48 = 16 tiles x 3 tensors). Zeroed per call.
__device__ int g_done[BATCH];

// Perfect-wave retention schedule: 17 CTAs per batch, each exactly 8 iters.
__constant__ int s0_qt[17] = {15,15,14,14,13,13,12,12,11,11,10,10, 9, 9, 8, 8, 7};
__constant__ int s0_j0[17] = { 0, 8, 0, 8, 0, 8, 0, 8, 0, 8, 0, 8, 0, 8, 0, 8, 0};
__constant__ int s0_j1[17] = { 8,16, 8,15, 8,14, 8,13, 8,12, 8,11, 8,10, 8, 9, 8};
__constant__ int s1_qt[17] = {-1,-1,-1, 0,-1, 1,-1, 2,-1, 3,-1, 4,-1, 5,-1, 6,-1};

// ---------------------------------------------------------------------------
// PTX helpers (family-generic)
// ---------------------------------------------------------------------------
__device__ __forceinline__ uint32_t smem_u32(const void* p) {
    uint32_t a;
    asm("{ .reg .u64 t; cvta.to.shared.u64 t, %1; cvt.u32.u64 %0, t; }"
        : "=r"(a) : "l"(p));
    return a;
}

__device__ __forceinline__ void mma16816(float* c,
    uint32_t a0, uint32_t a1, uint32_t a2, uint32_t a3,
    uint32_t b0, uint32_t b1)
{
    asm volatile(
        "mma.sync.aligned.m16n8k16.row.col.f32.f16.f16.f32 "
        "{%0,%1,%2,%3}, {%4,%5,%6,%7}, {%8,%9}, {%0,%1,%2,%3};"
        : "+f"(c[0]), "+f"(c[1]), "+f"(c[2]), "+f"(c[3])
        : "r"(a0), "r"(a1), "r"(a2), "r"(a3), "r"(b0), "r"(b1));
}

__device__ __forceinline__ void ldm_x4(uint32_t& r0, uint32_t& r1,
                                       uint32_t& r2, uint32_t& r3, uint32_t addr)
{
    asm volatile("ldmatrix.sync.aligned.m8n8.x4.shared.b16 {%0,%1,%2,%3}, [%4];"
                 : "=r"(r0), "=r"(r1), "=r"(r2), "=r"(r3) : "r"(addr));
}

#define CP_ASYNC16(dst, src) \
    asm volatile("cp.async.cg.shared.global [%0], [%1], 16;" :: "r"(dst), "l"(src))
#define CP_COMMIT() asm volatile("cp.async.commit_group;" ::: "memory")
#define CP_WAIT(n)  asm volatile("cp.async.wait_group %0;" :: "n"(n) : "memory")

#define RED_ADD_F32(addr, val) \
    asm volatile("red.global.add.f32 [%0], %1;" :: "l"(addr), "f"(val) : "memory")

__device__ __forceinline__ uint32_t cvt2h(float a0, float a1) {
    __half2 h = __float22half2_rn(make_float2(a0, a1));
    return *reinterpret_cast<uint32_t*>(&h);
}

// ---------------------------------------------------------------------------
// Kernel 0: convert W to fp16, layout [w][n][k] (coalesced smem transpose).
// ---------------------------------------------------------------------------
__global__ __launch_bounds__(256) void prep_w(
    const float* __restrict__ wq, const float* __restrict__ wk,
    const float* __restrict__ wv)
{
    __shared__ float tile[64 * 128];

    const int tid = threadIdx.x;
    const int kb  = blockIdx.x;
    const int w   = blockIdx.y;
    const float* W = (w == 0) ? wq : (w == 1) ? wk : wv;
    const int k0 = kb * 64;

#pragma unroll
    for (int it = 0; it < 8; it++) {
        int u = tid + it * 256;
        int r = u >> 5, c4 = (u & 31) * 4;
        *(float4*)&tile[r * 128 + c4] =
            *(const float4*)&W[(size_t)(k0 + r) * HEAD + c4];
    }
    __syncthreads();

    const int n  = tid >> 1;
    const int kh = (tid & 1) * 32;
    uint32_t packed[16];
#pragma unroll
    for (int i = 0; i < 16; i++)
        packed[i] = cvt2h(tile[(kh + 2 * i) * 128 + n],
                          tile[(kh + 2 * i + 1) * 128 + n]);

    uint4* dst = (uint4*)&g_w[((size_t)w * 128 + n) * 1024 + k0 + kh];
#pragma unroll
    for (int i = 0; i < 4; i++)
        dst[i] = make_uint4(packed[4*i], packed[4*i+1], packed[4*i+2], packed[4*i+3]);
}

// ---------------------------------------------------------------------------
// Fused kernel: proj role (bid 0..383) + retention role (bid 384..519).
// ---------------------------------------------------------------------------
#define PKPAD 72
#define PABUF (128 * PKPAD * 2)
#define PSM_TOTAL (4 * PABUF)       // 73728 (proj role usage)

#define KPAD 136
#define RB (128 * KPAD * 2)
#define SMR_BYTES (5 * RB)          // 174080 (retention role usage = kernel smem)

#define NPROJ (NTILES * 3)          // 384
#define NRET  (BATCH * 17)          // 136

// ---- proj warp GEMM (round-11 proven) ----
__device__ __forceinline__ void warp_gemm_proj(float acc[4][4][4],
    uint32_t sA, uint32_t sW, uint32_t a_lane, uint32_t b_lane)
{
#pragma unroll
    for (int ks = 0; ks < 4; ks++) {
        const uint32_t kso = (uint32_t)(ks * 16) * 2;
        uint32_t ah[4][4];
#pragma unroll
        for (int mt = 0; mt < 4; mt++) {
            const uint32_t ao = a_lane + (uint32_t)(mt * 16 * PKPAD) * 2 + kso;
            ldm_x4(ah[mt][0], ah[mt][1], ah[mt][2], ah[mt][3], sA + ao);
        }
#pragma unroll
        for (int np = 0; np < 2; np++) {
            const uint32_t bo = b_lane + (uint32_t)(np * 16 * PKPAD) * 2 + kso;
            uint32_t bh[4];
            ldm_x4(bh[0], bh[1], bh[2], bh[3], sW + bo);
#pragma unroll
            for (int mt = 0; mt < 4; mt++) {
                mma16816(acc[mt][2*np],   ah[mt][0], ah[mt][1], ah[mt][2], ah[mt][3], bh[0], bh[1]);
                mma16816(acc[mt][2*np+1], ah[mt][0], ah[mt][1], ah[mt][2], ah[mt][3], bh[2], bh[3]);
            }
        }
    }
}

__device__ __forceinline__ void cpa_tile(uint32_t dst, const __half* __restrict__ src,
                                         int tid) {
#pragma unroll
    for (int it = 0; it < 8; it++) {
        int u = tid + it * 256;
        int row = u >> 4, c = u & 15;
        CP_ASYNC16(dst + (uint32_t)(row * KPAD + c * 8) * 2, (const char*)src + (size_t)u * 16);
    }
}

// ---- proj role body ----
__device__ void proj_role(char* psm, int bid,
    const float* __restrict__ in_key,
    const float* __restrict__ in_query,
    const float* __restrict__ in_value)
{
    const uint32_t sb = smem_u32(psm);

    const int p    = bid % 3;
    const int tile = bid / 3;
    const float* A;
    if (p == 0)      A = in_query;
    else if (p == 1) A = in_key;
    else             A = in_value;

    const int tid  = threadIdx.x;
    const int wid  = tid >> 5, lane = tid & 31;
    const int g    = lane >> 2, t = lane & 3;
    const int mbase = (wid & 1) * 64;
    const int nbase = (wid >> 1) * 32;
    const int rowBase = tile * 128;

    const uint32_t a_lane = ((mbase + (lane & 15)) * PKPAD + (lane >> 4) * 8) * 2;
    const uint32_t b_lane = ((nbase + (lane & 7) + ((lane >> 4) << 3)) * PKPAD
                             + ((lane >> 3) & 1) * 8) * 2;

    const int aRow0 = tid >> 4;
    const int aC4   = (tid & 15) * 4;

    float acc[4][4][4];
#pragma unroll
    for (int i = 0; i < 4; i++)
#pragma unroll
        for (int j = 0; j < 4; j++)
#pragma unroll
            for (int q = 0; q < 4; q++) acc[i][j][q] = 0.0f;

    const __half* wsrc = g_w + (size_t)p * 128 * 1024;

    auto cpa_w = [&](int kb, int s) {
        uint32_t dw = sb + (2 + s) * PABUF;
#pragma unroll
        for (int it = 0; it < 4; it++) {
            int u = tid + it * 256;
            int row = u >> 3, c = u & 7;
            uint32_t doff = (uint32_t)(row * PKPAD + c * 8) * 2;
            size_t soff = (size_t)row * 1024 + kb * 64 + c * 8;
            CP_ASYNC16(dw + doff, (const char*)(wsrc + soff));
        }
        CP_COMMIT();
    };

    auto conv_a = [&](const float4* areg, int s) {
        const uint32_t dA = sb + s * PABUF;
#pragma unroll
        for (int it = 0; it < 8; it++) {
            uint32_t h0 = cvt2h(areg[it].x, areg[it].y);
            uint32_t h1 = cvt2h(areg[it].z, areg[it].w);
            uint32_t doff = (uint32_t)((aRow0 + it * 16) * PKPAD + aC4) * 2;
            asm volatile("st.shared.v2.b32 [%0], {%1,%2};" :: "r"(dA + doff), "r"(h0), "r"(h1));
        }
    };

    float4 areg[8];
#pragma unroll
    for (int it = 0; it < 8; it++)
        areg[it] = *(const float4*)&A[(size_t)(rowBase + aRow0 + it * 16) * EMB + aC4];
    conv_a(areg, 0);
#pragma unroll
    for (int it = 0; it < 8; it++)
        areg[it] = *(const float4*)&A[(size_t)(rowBase + aRow0 + it * 16) * EMB + 64 + aC4];
    cpa_w(0, 0);

    for (int kb = 0; kb < 16; kb++) {
        CP_WAIT(0);
        __syncthreads();

        if (kb < 15) {
            cpa_w(kb + 1, (kb + 1) & 1);
            conv_a(areg, (kb + 1) & 1);
        }
        if (kb < 14) {
            const int k0n = (kb + 2) * 64;
#pragma unroll
            for (int it = 0; it < 8; it++)
                areg[it] = *(const float4*)&A[(size_t)(rowBase + aRow0 + it * 16) * EMB + k0n + aC4];
        }

        const uint32_t sA = sb + (kb & 1) * PABUF;
        const uint32_t sW = sb + (2 + (kb & 1)) * PABUF;
        warp_gemm_proj(acc, sA, sW, a_lane, b_lane);
    }

    const size_t base = (size_t)tile * TILE_ELE;

    if (p != 2) {
        __half* dst = (p == 0) ? g_q : g_k;
#pragma unroll
        for (int mt = 0; mt < 4; mt++)
#pragma unroll
            for (int nt = 0; nt < 4; nt++) {
                int r0 = mbase + mt * 16 + g;
                int c  = nbase + nt * 8 + t * 2;
                *(uint32_t*)(dst + base + (size_t)r0 * 128 + c) =
                    cvt2h(acc[mt][nt][0], acc[mt][nt][1]);
                *(uint32_t*)(dst + base + (size_t)(r0 + 8) * 128 + c) =
                    cvt2h(acc[mt][nt][2], acc[mt][nt][3]);
            }
    } else {
        // V: transposed [h][n]
#pragma unroll
        for (int mt = 0; mt < 4; mt++)
#pragma unroll
            for (int nt = 0; nt < 4; nt++)
#pragma unroll
                for (int q = 0; q < 4; q++) {
                    int row = mbase + mt * 16 + g + (q >> 1) * 8;
                    int col = nbase + nt * 8 + t * 2 + (q & 1);
                    g_v[base + (size_t)col * 128 + row] = __float2half(acc[mt][nt][q]);
                }
    }

    // Publish: all stores visible at GPU scope, then bump the batch counter.
    __threadfence();
    __syncthreads();
    if (tid == 0) atomicAdd(&g_done[tile >> 4], 1);
}

// ---- retention role body (round-16 proven, plus readiness spin) ----
__device__ void retention_role(char* smraw, int bid, float* __restrict__ out)
{
    const uint32_t sb = smem_u32(smraw);
    const uint32_t sQ  = sb;
    const uint32_t sK0 = sb + RB;
    const uint32_t sV0 = sb + 3*RB;

    const int tid  = threadIdx.x;
    const int wid  = tid >> 5, lane = tid & 31;
    const int g    = lane >> 2, t = lane & 3;

    const int rcid = bid - NPROJ;       // 0..135
    const int b    = rcid / 17;
    const int cid  = rcid % 17;

    // Wait until batch b fully projected (48 tiles).
    if (tid == 0) {
        while (atomicAdd(&g_done[b], 0) < 48)
            __nanosleep(200);
    }
    __syncthreads();

    const uint32_t a_lane = (uint32_t)((16 * wid + (lane & 15)) * KPAD + (lane >> 4) * 8) * 2;
    const uint32_t b_lane = (uint32_t)(((lane & 7) + ((lane >> 4) << 3)) * KPAD
                                       + ((lane >> 3) & 1) * 8) * 2;
    const int r0 = 16 * wid + g;

#pragma unroll 1
    for (int seg = 0; seg < 2; seg++) {
        int qt, j0, j1;
        if (seg == 0) { qt = s0_qt[cid]; j0 = s0_j0[cid]; j1 = s0_j1[cid]; }
        else          { qt = s1_qt[cid]; j0 = 0; j1 = qt + 1; if (qt < 0) break; }

        const int qtile = b * 16 + qt;

        cpa_tile(sQ, g_q + (size_t)qtile * TILE_ELE, tid);
        {
            const size_t kt = (size_t)(b * 16 + j0) * TILE_ELE;
            cpa_tile(sK0 + (uint32_t)(j0 & 1) * RB, g_k + kt, tid);
            cpa_tile(sV0 + (uint32_t)(j0 & 1) * RB, g_v + kt, tid);
        }
        CP_COMMIT();
        CP_WAIT(0);
        __syncthreads();

        float oacc[16][4];
#pragma unroll
        for (int i = 0; i < 16; i++)
#pragma unroll
            for (int q = 0; q < 4; q++) oacc[i][q] = 0.0f;

        for (int j = j0; j < j1; j++) {
            if (j + 1 < j1) {
                const size_t kt = (size_t)(b * 16 + j + 1) * TILE_ELE;
                cpa_tile(sK0 + (uint32_t)((j + 1) & 1) * RB, g_k + kt, tid);
                cpa_tile(sV0 + (uint32_t)((j + 1) & 1) * RB, g_v + kt, tid);
                CP_COMMIT();
            }

            const uint32_t sKc = sK0 + (uint32_t)(j & 1) * RB;
            const uint32_t sVc = sV0 + (uint32_t)(j & 1) * RB;

            float sacc[16][4];
#pragma unroll
            for (int i = 0; i < 16; i++)
#pragma unroll
                for (int q = 0; q < 4; q++) sacc[i][q] = 0.0f;

#pragma unroll 2
            for (int ks = 0; ks < 8; ks++) {
                const uint32_t kso = (uint32_t)(ks * 16) * 2;
                uint32_t ah[4];
                ldm_x4(ah[0], ah[1], ah[2], ah[3], sQ + a_lane + kso);
#pragma unroll
                for (int nb = 0; nb < 8; nb++) {
                    const uint32_t boff = b_lane + (uint32_t)(nb * 16 * KPAD) * 2 + kso;
                    uint32_t bh[4];
                    ldm_x4(bh[0], bh[1], bh[2], bh[3], sKc + boff);
                    mma16816(sacc[2*nb],   ah[0], ah[1], ah[2], ah[3], bh[0], bh[1]);
                    mma16816(sacc[2*nb+1], ah[0], ah[1], ah[2], ah[3], bh[2], bh[3]);
                }
            }

            if (j == qt) {
#pragma unroll
                for (int nt = 0; nt < 16; nt++) {
                    const int c0 = nt * 8 + t * 2;
                    if (c0     > r0)     sacc[nt][0] = 0.0f;
                    if (c0 + 1 > r0)     sacc[nt][1] = 0.0f;
                    if (c0     > r0 + 8) sacc[nt][2] = 0.0f;
                    if (c0 + 1 > r0 + 8) sacc[nt][3] = 0.0f;
                }
            }

#pragma unroll
            for (int ks = 0; ks < 8; ks++) {
                uint32_t sh[4];
                sh[0] = cvt2h(sacc[2*ks][0],   sacc[2*ks][1]);
                sh[1] = cvt2h(sacc[2*ks][2],   sacc[2*ks][3]);
                sh[2] = cvt2h(sacc[2*ks+1][0], sacc[2*ks+1][1]);
                sh[3] = cvt2h(sacc[2*ks+1][2], sacc[2*ks+1][3]);
                const uint32_t kso = (uint32_t)(ks * 16) * 2;
#pragma unroll
                for (int hb = 0; hb < 8; hb++) {
                    const uint32_t boff = b_lane + (uint32_t)(hb * 16 * KPAD) * 2 + kso;
                    uint32_t vh[4];
                    ldm_x4(vh[0], vh[1], vh[2], vh[3], sVc + boff);
                    mma16816(oacc[2*hb],   sh[0], sh[1], sh[2], sh[3], vh[0], vh[1]);
                    mma16816(oacc[2*hb+1], sh[0], sh[1], sh[2], sh[3], vh[2], vh[3]);
                }
            }

            if (j + 1 < j1) {
                CP_WAIT(0);
                __syncthreads();
            }
        }

        const size_t rowbase = (size_t)b * SEQ + (size_t)qt * 128;
        if (qt < 8) {
#pragma unroll
            for (int ht = 0; ht < 16; ht++) {
                int c = ht * 8 + t * 2;
                *(float2*)&out[(rowbase + r0) * HEAD + c]     = make_float2(oacc[ht][0], oacc[ht][1]);
                *(float2*)&out[(rowbase + r0 + 8) * HEAD + c] = make_float2(oacc[ht][2], oacc[ht][3]);
            }
        } else {
#pragma unroll
            for (int ht = 0; ht < 16; ht++) {
                int c = ht * 8 + t * 2;
                float* p0 = &out[(rowbase + r0) * HEAD + c];
                float* p1 = &out[(rowbase + r0 + 8) * HEAD + c];
                RED_ADD_F32(p0,     oacc[ht][0]);
                RED_ADD_F32(p0 + 1, oacc[ht][1]);
                RED_ADD_F32(p1,     oacc[ht][2]);
                RED_ADD_F32(p1 + 1, oacc[ht][3]);
            }
        }

        if (seg == 0 && s1_qt[cid] >= 0) __syncthreads();
    }
}

__global__ __launch_bounds__(256) void fused_tc(
    const float* __restrict__ in_key,
    const float* __restrict__ in_query,
    const float* __restrict__ in_value,
    float* __restrict__ out)
{
    extern __shared__ __align__(16) char smraw[];
    const int bid = blockIdx.x;
    if (bid < NPROJ) proj_role(smraw, bid, in_key, in_query, in_value);
    else             retention_role(smraw, bid, out);
}

// ---------------------------------------------------------------------------
// Launch
// ---------------------------------------------------------------------------
extern "C" void kernel_launch(void* const* d_in, const int* in_sizes, int n_in,
                              void* d_out, int out_size)
{
    const float* key   = (const float*)d_in[0];
    const float* query = (const float*)d_in[1];
    const float* value = (const float*)d_in[2];
    const float* w_q   = (const float*)d_in[3];
    const float* w_k   = (const float*)d_in[4];
    const float* w_v   = (const float*)d_in[5];
    float* out = (float*)d_out;

    // Zero output (red.add targets) and the per-batch counters.
    cudaMemsetAsync(out, 0, (size_t)out_size * sizeof(float));
    void* doneAddr = nullptr;
    cudaGetSymbolAddress(&doneAddr, g_done);
    cudaMemsetAsync(doneAddr, 0, BATCH * sizeof(int));

    dim3 gw(EMB / 64, 3);
    prep_w<<<gw, 256>>>(w_q, w_k, w_v);

    cudaFuncSetAttribute(fused_tc,
                         cudaFuncAttributeMaxDynamicSharedMemorySize, SMR_BYTES);
    fused_tc<<<NPROJ + NRET, 256, SMR_BYTES>>>(key, query, value, out);
}